// round 1
// baseline (speedup 1.0000x reference)
#include <cuda_runtime.h>
#include <cuda_bf16.h>
#include <mma.h>
#include <math_constants.h>

using namespace nvcuda;

#define BATCH 2
#define SEQ   2048
#define DM    1024
#define NH    16
#define DK    64
#define M_TOT (BATCH*SEQ)   // 4096

// -------- scratch (device globals: allocation-free) --------
__device__ float g_Q[(size_t)BATCH*NH*SEQ*DK];
__device__ float g_K[(size_t)BATCH*NH*SEQ*DK];
__device__ float g_V[(size_t)BATCH*NH*SEQ*DK];
__device__ float g_ctx[(size_t)M_TOT*DM];

// ============================================================
// TF32 WMMA GEMM:  C[M,N] = A[M,1024] * W[N,1024]^T + bias[N]
// MODE 0: A = x, writes Q/K/V scratch in [B,H,T,dk] layout
// MODE 1: A = g_ctx, writes Cout[M,DM]
// Block tile 128x128, BK=32. 256 threads = 8 warps (4x2),
// each warp computes 32x64 via 2x4 m16n16k8 fragments.
// ============================================================
template<int MODE>
__global__ __launch_bounds__(256)
void gemm_tf32_kernel(const float* __restrict__ A,
                      const float* __restrict__ W,
                      const float* __restrict__ bias,
                      float* __restrict__ Cout)
{
    constexpr int BK  = 32;
    constexpr int LDT = 36;   // padded smem ld (multiple of 4)
    __shared__ float As[128*LDT];
    __shared__ float Bs[128*LDT];
    __shared__ float stage[8*16*20];

    const int tid  = threadIdx.x;
    const int warp = tid >> 5;
    const int lane = tid & 31;
    const int wm   = warp >> 1;   // 0..3 -> m offset wm*32
    const int wn   = warp & 1;    // 0..1 -> n offset wn*64
    const int bm   = blockIdx.y;
    const int bn   = blockIdx.x;

    const float* Ap = (MODE == 1) ? g_ctx : A;

    wmma::fragment<wmma::accumulator,16,16,8,float> acc[2][4];
    #pragma unroll
    for (int i=0;i<2;i++)
        #pragma unroll
        for (int j=0;j<4;j++) wmma::fill_fragment(acc[i][j], 0.0f);

    const float* Ab = Ap + (size_t)(bm*128)*1024;
    const float* Wb = W  + (size_t)(bn*128)*1024;

    for (int k0 = 0; k0 < 1024; k0 += BK) {
        // load 128x32 tiles as float4, convert to tf32
        #pragma unroll
        for (int it = 0; it < 4; it++) {
            int idx = tid + it*256;         // 0..1023 float4 slots
            int r   = idx >> 3;
            int c4  = (idx & 7) << 2;
            float4 va = *(const float4*)(Ab + (size_t)r*1024 + k0 + c4);
            As[r*LDT + c4 + 0] = wmma::__float_to_tf32(va.x);
            As[r*LDT + c4 + 1] = wmma::__float_to_tf32(va.y);
            As[r*LDT + c4 + 2] = wmma::__float_to_tf32(va.z);
            As[r*LDT + c4 + 3] = wmma::__float_to_tf32(va.w);
            float4 vb = *(const float4*)(Wb + (size_t)r*1024 + k0 + c4);
            Bs[r*LDT + c4 + 0] = wmma::__float_to_tf32(vb.x);
            Bs[r*LDT + c4 + 1] = wmma::__float_to_tf32(vb.y);
            Bs[r*LDT + c4 + 2] = wmma::__float_to_tf32(vb.z);
            Bs[r*LDT + c4 + 3] = wmma::__float_to_tf32(vb.w);
        }
        __syncthreads();

        #pragma unroll
        for (int kk = 0; kk < BK; kk += 8) {
            wmma::fragment<wmma::matrix_a,16,16,8,wmma::precision::tf32,wmma::row_major> af[2];
            wmma::fragment<wmma::matrix_b,16,16,8,wmma::precision::tf32,wmma::col_major> bf[4];
            #pragma unroll
            for (int i=0;i<2;i++)
                wmma::load_matrix_sync(af[i], &As[(wm*32 + i*16)*LDT + kk], LDT);
            #pragma unroll
            for (int j=0;j<4;j++)
                wmma::load_matrix_sync(bf[j], &Bs[(wn*64 + j*16)*LDT + kk], LDT);
            #pragma unroll
            for (int i=0;i<2;i++)
                #pragma unroll
                for (int j=0;j<4;j++)
                    wmma::mma_sync(acc[i][j], af[i], bf[j], acc[i][j]);
        }
        __syncthreads();
    }

    // epilogue via per-warp staging
    float* st = stage + warp*16*20;
    #pragma unroll
    for (int i=0;i<2;i++) {
        #pragma unroll
        for (int j=0;j<4;j++) {
            wmma::store_matrix_sync(st, acc[i][j], 20, wmma::mem_row_major);
            __syncwarp();
            #pragma unroll
            for (int e=0;e<8;e++) {
                int idx = e*32 + lane;
                int r = idx >> 4, c = idx & 15;
                int gm = bm*128 + wm*32 + i*16 + r;
                int gn = bn*128 + wn*64 + j*16 + c;
                float v = st[r*20 + c] + bias[gn];
                if (MODE == 0) {
                    int b = gm >> 11, t = gm & 2047;
                    int part = gn >> 10, rem = gn & 1023;
                    int h = rem >> 6, d = rem & 63;
                    float* dst = (part == 0) ? g_Q : ((part == 1) ? g_K : g_V);
                    dst[(((size_t)(b*NH + h))*SEQ + t)*DK + d] = v;
                } else {
                    Cout[(size_t)gm*DM + gn] = v;
                }
            }
            __syncwarp();
        }
    }
}

// ============================================================
// Flash-style attention: one CTA handles (b, h, 64 queries).
// Streams 64-key tiles; TF32 WMMA for S=QK^T and O+=P*V;
// O and online-softmax state in smem fp32.
// 128 threads = 4 warps; warp w owns S/O rows [w*16, w*16+16).
// ============================================================
#define ALD 68
#define ATTN_SMEM ((5*64*ALD + 128)*4)

__global__ __launch_bounds__(128)
void attn_kernel()
{
    extern __shared__ float sm[];
    float* Qs   = sm;                 // 64 x 68 (tf32, pre-scaled by 1/8)
    float* Ks   = Qs + 64*ALD;        // 64 x 68 (tf32)
    float* Vs   = Ks + 64*ALD;        // 64 x 68 (tf32)
    float* Ps   = Vs + 64*ALD;        // 64 x 68 (S then P)
    float* Os   = Ps + 64*ALD;        // 64 x 68 (fp32 accum)
    float* rowm = Os + 64*ALD;        // 64
    float* rowl = rowm + 64;          // 64

    const int tid  = threadIdx.x;
    const int warp = tid >> 5;
    const int q0   = blockIdx.x * 64;
    const int h    = blockIdx.y;
    const int b    = blockIdx.z;
    const size_t headbase = ((size_t)(b*NH + h))*SEQ*DK;

    // Load Q tile (scaled by 1/sqrt(dk)=0.125), init O/m/l
    for (int i = tid; i < 64*64; i += 128) {
        int r = i >> 6, d = i & 63;
        Qs[r*ALD + d] = wmma::__float_to_tf32(g_Q[headbase + (size_t)(q0 + r)*DK + d] * 0.125f);
    }
    for (int i = tid; i < 64*ALD; i += 128) Os[i] = 0.0f;
    if (tid < 64) { rowm[tid] = -CUDART_INF_F; rowl[tid] = 0.0f; }
    __syncthreads();

    for (int kt = 0; kt < SEQ/64; kt++) {
        const size_t kb = headbase + (size_t)kt*64*DK;
        for (int i = tid; i < 64*64; i += 128) {
            int r = i >> 6, d = i & 63;
            Ks[r*ALD + d] = wmma::__float_to_tf32(g_K[kb + (size_t)r*DK + d]);
            Vs[r*ALD + d] = wmma::__float_to_tf32(g_V[kb + (size_t)r*DK + d]);
        }
        __syncthreads();

        // ---- S = Q * K^T : warp computes 16x64 strip ----
        {
            wmma::fragment<wmma::accumulator,16,16,8,float> sacc[4];
            #pragma unroll
            for (int j=0;j<4;j++) wmma::fill_fragment(sacc[j], 0.0f);
            #pragma unroll
            for (int k0 = 0; k0 < 64; k0 += 8) {
                wmma::fragment<wmma::matrix_a,16,16,8,wmma::precision::tf32,wmma::row_major> af;
                wmma::load_matrix_sync(af, &Qs[(warp*16)*ALD + k0], ALD);
                #pragma unroll
                for (int j=0;j<4;j++) {
                    wmma::fragment<wmma::matrix_b,16,16,8,wmma::precision::tf32,wmma::col_major> bf;
                    wmma::load_matrix_sync(bf, &Ks[(j*16)*ALD + k0], ALD);
                    wmma::mma_sync(sacc[j], af, bf, sacc[j]);
                }
            }
            #pragma unroll
            for (int j=0;j<4;j++)
                wmma::store_matrix_sync(&Ps[(warp*16)*ALD + j*16], sacc[j], ALD, wmma::mem_row_major);
        }
        __syncthreads();

        // ---- online softmax: 2 threads per row ----
        {
            int r = tid >> 1, half = tid & 1;
            float* Sr = Ps + r*ALD + half*32;
            float mx = -CUDART_INF_F;
            #pragma unroll
            for (int c=0;c<32;c++) mx = fmaxf(mx, Sr[c]);
            mx = fmaxf(mx, __shfl_xor_sync(0xffffffffu, mx, 1));
            float mold = rowm[r];
            float mnew = fmaxf(mold, mx);
            float alpha = __expf(mold - mnew);   // exp(-inf)=0 on first tile
            float s = 0.0f;
            #pragma unroll
            for (int c=0;c<32;c++) {
                float p = __expf(Sr[c] - mnew);
                s += p;
                Sr[c] = wmma::__float_to_tf32(p);
            }
            s += __shfl_xor_sync(0xffffffffu, s, 1);
            if (!half) { rowm[r] = mnew; rowl[r] = rowl[r]*alpha + s; }
            float* Or = Os + r*ALD + half*32;
            #pragma unroll
            for (int c=0;c<32;c++) Or[c] *= alpha;
        }
        __syncthreads();

        // ---- O += P * V ----
        {
            wmma::fragment<wmma::accumulator,16,16,8,float> oacc[4];
            #pragma unroll
            for (int j=0;j<4;j++)
                wmma::load_matrix_sync(oacc[j], &Os[(warp*16)*ALD + j*16], ALD, wmma::mem_row_major);
            #pragma unroll
            for (int k0 = 0; k0 < 64; k0 += 8) {
                wmma::fragment<wmma::matrix_a,16,16,8,wmma::precision::tf32,wmma::row_major> af;
                wmma::load_matrix_sync(af, &Ps[(warp*16)*ALD + k0], ALD);
                #pragma unroll
                for (int j=0;j<4;j++) {
                    wmma::fragment<wmma::matrix_b,16,16,8,wmma::precision::tf32,wmma::row_major> bf;
                    wmma::load_matrix_sync(bf, &Vs[k0*ALD + j*16], ALD);
                    wmma::mma_sync(oacc[j], af, bf, oacc[j]);
                }
            }
            #pragma unroll
            for (int j=0;j<4;j++)
                wmma::store_matrix_sync(&Os[(warp*16)*ALD + j*16], oacc[j], ALD, wmma::mem_row_major);
        }
        __syncthreads();
    }

    // ---- normalize + write ctx in [B,T,DM] ----
    {
        int r = tid >> 1, half = tid & 1;
        float inv = 1.0f / rowl[r];
        float* Or  = Os + r*ALD + half*32;
        float* dst = g_ctx + ((size_t)(b*SEQ + q0 + r))*DM + h*DK + half*32;
        #pragma unroll
        for (int c=0;c<32;c++) dst[c] = Or[c] * inv;
    }
}

// ============================================================
extern "C" void kernel_launch(void* const* d_in, const int* in_sizes, int n_in,
                              void* d_out, int out_size)
{
    (void)in_sizes; (void)n_in; (void)out_size;
    const float* x     = (const float*)d_in[0];
    const float* w_qkv = (const float*)d_in[1];
    const float* b_qkv = (const float*)d_in[2];
    const float* w_out = (const float*)d_in[3];
    const float* b_out = (const float*)d_in[4];
    float* out = (float*)d_out;

    cudaFuncSetAttribute(attn_kernel, cudaFuncAttributeMaxDynamicSharedMemorySize, ATTN_SMEM);

    // 1) QKV projection -> Q/K/V scratch
    gemm_tf32_kernel<0><<<dim3(3*DM/128, M_TOT/128), 256>>>(x, w_qkv, b_qkv, nullptr);
    // 2) attention -> ctx scratch
    attn_kernel<<<dim3(SEQ/64, NH, BATCH), 128, ATTN_SMEM>>>();
    // 3) output projection -> d_out
    gemm_tf32_kernel<1><<<dim3(DM/128, M_TOT/128), 256>>>(nullptr, w_out, b_out, out);
}

// round 5
// speedup vs baseline: 2.2772x; 2.2772x over previous
#include <cuda_runtime.h>
#include <cuda_fp16.h>
#include <mma.h>
#include <math_constants.h>

using namespace nvcuda;

#define BATCH 2
#define SEQ   2048
#define DM    1024
#define NH    16
#define DK    64
#define M_TOT (BATCH*SEQ)   // 4096

// -------- scratch (device globals: allocation-free) --------
__device__ float  g_Q[(size_t)BATCH*NH*SEQ*DK];
__device__ float  g_K[(size_t)BATCH*NH*SEQ*DK];
__device__ __half g_V[(size_t)BATCH*NH*SEQ*DK];
__device__ float  g_ctx[(size_t)M_TOT*DM];

// -------- cp.async helpers --------
__device__ __forceinline__ void cp_async16(void* smem, const void* gmem) {
    unsigned s = (unsigned)__cvta_generic_to_shared(smem);
    asm volatile("cp.async.cg.shared.global [%0], [%1], 16;\n" :: "r"(s), "l"(gmem));
}
__device__ __forceinline__ void cp_commit() { asm volatile("cp.async.commit_group;\n"); }
template<int N> __device__ __forceinline__ void cp_wait() {
    asm volatile("cp.async.wait_group %0;\n" :: "n"(N));
}
__device__ __forceinline__ unsigned h2_as_u32(__half2 h) {
    return *reinterpret_cast<unsigned*>(&h);
}

// ============================================================
// TF32 WMMA GEMM:  C[M,N] = A[M,1024] * W[N,1024]^T + bias[N]
// cp.async double-buffered. MODE 0: writes Q/K (fp32) + V (fp16)
// scratch in [B,H,T,dk]. MODE 1: A=g_ctx, writes Cout[M,DM].
// 128x128 tile, BK=32, 256 thr = 8 warps, warp tile 32x64.
// ============================================================
#define G_LDT 36
#define GEMM_SMEM ((2*128*G_LDT*2 + 8*16*20)*4)

template<int MODE>
__global__ __launch_bounds__(256, 2)
void gemm_tf32_kernel(const float* __restrict__ A,
                      const float* __restrict__ W,
                      const float* __restrict__ bias,
                      float* __restrict__ Cout)
{
    extern __shared__ float sm[];
    float* As    = sm;                       // 2 x 128 x 36
    float* Bs    = sm + 2*128*G_LDT;         // 2 x 128 x 36
    float* stage = sm + 4*128*G_LDT;         // 8 x 16 x 20

    const int tid  = threadIdx.x;
    const int warp = tid >> 5;
    const int lane = tid & 31;
    const int wm   = warp >> 1;
    const int wn   = warp & 1;
    const int bm   = blockIdx.y;
    const int bn   = blockIdx.x;

    const float* Ap = (MODE == 1) ? g_ctx : A;
    const float* Ab = Ap + (size_t)(bm*128)*1024;
    const float* Wb = W  + (size_t)(bn*128)*1024;

    wmma::fragment<wmma::accumulator,16,16,8,float> acc[2][4];
    #pragma unroll
    for (int i=0;i<2;i++)
        #pragma unroll
        for (int j=0;j<4;j++) wmma::fill_fragment(acc[i][j], 0.0f);

    auto preload = [&](int ki, int st) {
        float* as = As + st*128*G_LDT;
        float* bs = Bs + st*128*G_LDT;
        #pragma unroll
        for (int it = 0; it < 4; it++) {
            int idx = tid + it*256;
            int r   = idx >> 3;
            int c4  = (idx & 7) << 2;
            cp_async16(as + r*G_LDT + c4, Ab + (size_t)r*1024 + ki*32 + c4);
            cp_async16(bs + r*G_LDT + c4, Wb + (size_t)r*1024 + ki*32 + c4);
        }
    };

    preload(0, 0); cp_commit();
    preload(1, 1); cp_commit();

    for (int i = 0; i < 32; i++) {
        if (i < 31) cp_wait<1>(); else cp_wait<0>();
        __syncthreads();
        const float* as = As + (i&1)*128*G_LDT;
        const float* bs = Bs + (i&1)*128*G_LDT;
        #pragma unroll
        for (int kk = 0; kk < 32; kk += 8) {
            wmma::fragment<wmma::matrix_a,16,16,8,wmma::precision::tf32,wmma::row_major> af[2];
            wmma::fragment<wmma::matrix_b,16,16,8,wmma::precision::tf32,wmma::col_major> bf[4];
            #pragma unroll
            for (int x=0;x<2;x++)
                wmma::load_matrix_sync(af[x], &as[(wm*32 + x*16)*G_LDT + kk], G_LDT);
            #pragma unroll
            for (int j=0;j<4;j++)
                wmma::load_matrix_sync(bf[j], &bs[(wn*64 + j*16)*G_LDT + kk], G_LDT);
            #pragma unroll
            for (int x=0;x<2;x++)
                #pragma unroll
                for (int j=0;j<4;j++)
                    wmma::mma_sync(acc[x][j], af[x], bf[j], acc[x][j]);
        }
        __syncthreads();
        if (i + 2 < 32) { preload(i+2, i&1); cp_commit(); }
    }

    // epilogue via per-warp staging
    float* st = stage + warp*16*20;
    #pragma unroll
    for (int x=0;x<2;x++) {
        #pragma unroll
        for (int j=0;j<4;j++) {
            wmma::store_matrix_sync(st, acc[x][j], 20, wmma::mem_row_major);
            __syncwarp();
            #pragma unroll
            for (int e=0;e<8;e++) {
                int idx = e*32 + lane;
                int r = idx >> 4, c = idx & 15;
                int gm = bm*128 + wm*32 + x*16 + r;
                int gn = bn*128 + wn*64 + j*16 + c;
                float v = st[r*20 + c] + bias[gn];
                if (MODE == 0) {
                    int b = gm >> 11, t = gm & 2047;
                    int part = gn >> 10, rem = gn & 1023;
                    int h = rem >> 6, d = rem & 63;
                    size_t off = (((size_t)(b*NH + h))*SEQ + t)*DK + d;
                    if (part == 0)      g_Q[off] = v;
                    else if (part == 1) g_K[off] = v;
                    else                g_V[off] = __float2half(v);
                } else {
                    Cout[(size_t)gm*DM + gn] = v;
                }
            }
            __syncwarp();
        }
    }
}

// ============================================================
// FlashAttention-2 style: CTA = (b, h, 128 queries), 8 warps,
// warp owns 16 rows. K tiles of 64 keys, cp.async double-buffered.
// S: mma.m16n8k8.tf32 (Q in regs, K from smem LDS).
// softmax fully in registers (quad shuffles).
// P->fp16 in regs, O += P*V via mma.m16n8k16.f16, V via ldmatrix.
// O never leaves registers until the final store.
// ============================================================
#define K_LD 68   // floats per K row
#define V_LD 72   // halves per V row
#define ATTN_SMEM (2*64*K_LD*4 + 2*64*V_LD*2)

__device__ __forceinline__ void mma_tf32(float* d, const unsigned* a, unsigned b0, unsigned b1) {
    asm volatile(
        "mma.sync.aligned.m16n8k8.row.col.f32.tf32.tf32.f32 "
        "{%0,%1,%2,%3},{%4,%5,%6,%7},{%8,%9},{%0,%1,%2,%3};\n"
        : "+f"(d[0]),"+f"(d[1]),"+f"(d[2]),"+f"(d[3])
        : "r"(a[0]),"r"(a[1]),"r"(a[2]),"r"(a[3]),"r"(b0),"r"(b1));
}
__device__ __forceinline__ void mma_f16(float* d, const unsigned* a, unsigned b0, unsigned b1) {
    asm volatile(
        "mma.sync.aligned.m16n8k16.row.col.f32.f16.f16.f32 "
        "{%0,%1,%2,%3},{%4,%5,%6,%7},{%8,%9},{%0,%1,%2,%3};\n"
        : "+f"(d[0]),"+f"(d[1]),"+f"(d[2]),"+f"(d[3])
        : "r"(a[0]),"r"(a[1]),"r"(a[2]),"r"(a[3]),"r"(b0),"r"(b1));
}

__global__ __launch_bounds__(256, 2)
void attn_kernel()
{
    extern __shared__ float sm[];
    float*  Ksm = sm;                                  // 2 x 64 x 68 fp32
    __half* Vsm = (__half*)(sm + 2*64*K_LD);           // 2 x 64 x 72 fp16

    const int tid  = threadIdx.x;
    const int warp = tid >> 5;
    const int lane = tid & 31;
    const int r    = lane >> 2;      // 0..7
    const int c    = lane & 3;       // 0..3
    const int q0   = blockIdx.x * 128;
    const int h    = blockIdx.y;
    const int b    = blockIdx.z;
    const size_t headbase = ((size_t)(b*NH + h))*SEQ*DK;

    // ---- load Q fragments (scaled by 1/8) straight from gmem ----
    unsigned qf[8][4];
    {
        const float* q_r0 = g_Q + headbase + (size_t)(q0 + warp*16 + r)*DK;
        const float* q_r1 = q_r0 + 8*DK;
        #pragma unroll
        for (int s = 0; s < 8; s++) {
            qf[s][0] = __float_as_uint(q_r0[8*s + c    ] * 0.125f);
            qf[s][1] = __float_as_uint(q_r1[8*s + c    ] * 0.125f);
            qf[s][2] = __float_as_uint(q_r0[8*s + c + 4] * 0.125f);
            qf[s][3] = __float_as_uint(q_r1[8*s + c + 4] * 0.125f);
        }
    }

    float Oacc[8][4];
    #pragma unroll
    for (int j=0;j<8;j++)
        #pragma unroll
        for (int e=0;e<4;e++) Oacc[j][e] = 0.0f;
    float mrow[2] = {-CUDART_INF_F, -CUDART_INF_F};
    float lrow[2] = {0.0f, 0.0f};

    auto preload = [&](int kt, int st) {
        const size_t kb = headbase + (size_t)kt*64*DK;
        float*  kd = Ksm + st*64*K_LD;
        __half* vd = Vsm + st*64*V_LD;
        #pragma unroll
        for (int it = 0; it < 4; it++) {                 // K: 1024 float4
            int idx = tid + it*256;
            int row = idx >> 4, c4 = (idx & 15) << 2;
            cp_async16(kd + row*K_LD + c4, g_K + kb + (size_t)row*DK + c4);
        }
        #pragma unroll
        for (int it = 0; it < 2; it++) {                 // V: 512 x 16B
            int idx = tid + it*256;
            int row = idx >> 3, c8 = (idx & 7) << 3;
            cp_async16(vd + row*V_LD + c8, g_V + kb + (size_t)row*DK + c8);
        }
    };

    preload(0, 0); cp_commit();
    preload(1, 1); cp_commit();

    const unsigned vbase0 = (unsigned)__cvta_generic_to_shared(Vsm);

    for (int kt = 0; kt < SEQ/64; kt++) {
        if (kt < SEQ/64 - 1) cp_wait<1>(); else cp_wait<0>();
        __syncthreads();
        const int st = kt & 1;
        const float* Kst  = Ksm + st*64*K_LD;
        const unsigned vb = vbase0 + (unsigned)(st*64*V_LD*2);

        // ---- S = Q K^T (tf32 mma, regs) ----
        float Sacc[8][4];
        #pragma unroll
        for (int j=0;j<8;j++)
            #pragma unroll
            for (int e=0;e<4;e++) Sacc[j][e] = 0.0f;
        #pragma unroll
        for (int s = 0; s < 8; s++) {
            #pragma unroll
            for (int j = 0; j < 8; j++) {
                const float* kp = Kst + (8*j + r)*K_LD + 8*s + c;
                unsigned b0 = __float_as_uint(kp[0]);
                unsigned b1 = __float_as_uint(kp[4]);
                mma_tf32(Sacc[j], qf[s], b0, b1);
            }
        }

        // ---- online softmax in registers ----
        float mx0 = Sacc[0][0], mx1 = Sacc[0][2];
        #pragma unroll
        for (int j=0;j<8;j++) {
            mx0 = fmaxf(mx0, fmaxf(Sacc[j][0], Sacc[j][1]));
            mx1 = fmaxf(mx1, fmaxf(Sacc[j][2], Sacc[j][3]));
        }
        mx0 = fmaxf(mx0, __shfl_xor_sync(0xffffffffu, mx0, 1));
        mx0 = fmaxf(mx0, __shfl_xor_sync(0xffffffffu, mx0, 2));
        mx1 = fmaxf(mx1, __shfl_xor_sync(0xffffffffu, mx1, 1));
        mx1 = fmaxf(mx1, __shfl_xor_sync(0xffffffffu, mx1, 2));
        float mn0 = fmaxf(mrow[0], mx0), mn1 = fmaxf(mrow[1], mx1);
        float al0 = __expf(mrow[0] - mn0), al1 = __expf(mrow[1] - mn1);
        mrow[0] = mn0; mrow[1] = mn1;

        unsigned ph[16];
        float sum0 = 0.0f, sum1 = 0.0f;
        #pragma unroll
        for (int j = 0; j < 8; j++) {
            float p0 = __expf(Sacc[j][0] - mn0);
            float p1 = __expf(Sacc[j][1] - mn0);
            float p2 = __expf(Sacc[j][2] - mn1);
            float p3 = __expf(Sacc[j][3] - mn1);
            sum0 += p0 + p1; sum1 += p2 + p3;
            ph[2*j  ] = h2_as_u32(__floats2half2_rn(p0, p1));
            ph[2*j+1] = h2_as_u32(__floats2half2_rn(p2, p3));
        }
        sum0 += __shfl_xor_sync(0xffffffffu, sum0, 1);
        sum0 += __shfl_xor_sync(0xffffffffu, sum0, 2);
        sum1 += __shfl_xor_sync(0xffffffffu, sum1, 1);
        sum1 += __shfl_xor_sync(0xffffffffu, sum1, 2);
        lrow[0] = lrow[0]*al0 + sum0;
        lrow[1] = lrow[1]*al1 + sum1;
        #pragma unroll
        for (int j=0;j<8;j++) {
            Oacc[j][0] *= al0; Oacc[j][1] *= al0;
            Oacc[j][2] *= al1; Oacc[j][3] *= al1;
        }

        // ---- O += P V (fp16 mma, V via ldmatrix.trans) ----
        const int t  = lane >> 3;     // 0..3 tile selector
        const int rr = lane & 7;
        #pragma unroll
        for (int s = 0; s < 4; s++) {
            const unsigned* af = &ph[4*s];
            #pragma unroll
            for (int g = 0; g < 4; g++) {
                unsigned addr = vb + (unsigned)(((16*s + (t&1)*8 + rr)*V_LD + (t>>1)*8 + g*16)*2);
                unsigned r0,r1,r2,r3;
                asm volatile(
                    "ldmatrix.sync.aligned.m8n8.x4.trans.shared.b16 {%0,%1,%2,%3}, [%4];\n"
                    : "=r"(r0),"=r"(r1),"=r"(r2),"=r"(r3) : "r"(addr));
                mma_f16(Oacc[2*g  ], af, r0, r1);
                mma_f16(Oacc[2*g+1], af, r2, r3);
            }
        }

        __syncthreads();
        if (kt + 2 < SEQ/64) { preload(kt+2, st); cp_commit(); }
    }

    // ---- normalize + write ctx [B,T,DM] ----
    {
        float inv0 = 1.0f / lrow[0];
        float inv1 = 1.0f / lrow[1];
        float* row0 = g_ctx + ((size_t)(b*SEQ + q0 + warp*16 + r    ))*DM + h*DK;
        float* row1 = g_ctx + ((size_t)(b*SEQ + q0 + warp*16 + r + 8))*DM + h*DK;
        #pragma unroll
        for (int j = 0; j < 8; j++) {
            float2 v0 = make_float2(Oacc[j][0]*inv0, Oacc[j][1]*inv0);
            float2 v1 = make_float2(Oacc[j][2]*inv1, Oacc[j][3]*inv1);
            *(float2*)(row0 + 8*j + 2*c) = v0;
            *(float2*)(row1 + 8*j + 2*c) = v1;
        }
    }
}

// ============================================================
extern "C" void kernel_launch(void* const* d_in, const int* in_sizes, int n_in,
                              void* d_out, int out_size)
{
    (void)in_sizes; (void)n_in; (void)out_size;
    const float* x     = (const float*)d_in[0];
    const float* w_qkv = (const float*)d_in[1];
    const float* b_qkv = (const float*)d_in[2];
    const float* w_out = (const float*)d_in[3];
    const float* b_out = (const float*)d_in[4];
    float* out = (float*)d_out;

    cudaFuncSetAttribute(gemm_tf32_kernel<0>, cudaFuncAttributeMaxDynamicSharedMemorySize, GEMM_SMEM);
    cudaFuncSetAttribute(gemm_tf32_kernel<1>, cudaFuncAttributeMaxDynamicSharedMemorySize, GEMM_SMEM);
    cudaFuncSetAttribute(attn_kernel, cudaFuncAttributeMaxDynamicSharedMemorySize, ATTN_SMEM);

    gemm_tf32_kernel<0><<<dim3(3*DM/128, M_TOT/128), 256, GEMM_SMEM>>>(x, w_qkv, b_qkv, nullptr);
    attn_kernel<<<dim3(SEQ/128, NH, BATCH), 256, ATTN_SMEM>>>();
    gemm_tf32_kernel<1><<<dim3(DM/128, M_TOT/128), 256, GEMM_SMEM>>>(nullptr, w_out, b_out, out);
}

// round 7
// speedup vs baseline: 6.4928x; 2.8512x over previous
#include <cuda_runtime.h>
#include <cuda_fp16.h>
#include <math_constants.h>
#include <cstdint>

#define BATCH 2
#define SEQ   2048
#define DM    1024
#define NH    16
#define DK    64
#define M_TOT (BATCH*SEQ)   // 4096

// -------- scratch (device globals: allocation-free) --------
__device__ __half g_Qh [(size_t)BATCH*NH*SEQ*DK];   // pre-scaled by 1/8
__device__ __half g_Kh [(size_t)BATCH*NH*SEQ*DK];
__device__ __half g_Vh [(size_t)BATCH*NH*SEQ*DK];
__device__ __half g_ctxh[(size_t)M_TOT*DM];
__device__ __half g_xh   [(size_t)M_TOT*DM];
__device__ __half g_wqkvh[(size_t)3*DM*DM];
__device__ __half g_wouth[(size_t)DM*DM];

// -------- helpers --------
__device__ __forceinline__ void cp_async16(uint32_t smem, const void* gmem) {
    asm volatile("cp.async.cg.shared.global [%0], [%1], 16;\n" :: "r"(smem), "l"(gmem));
}
__device__ __forceinline__ void cp_commit() { asm volatile("cp.async.commit_group;\n"); }
template<int N> __device__ __forceinline__ void cp_wait() {
    asm volatile("cp.async.wait_group %0;\n" :: "n"(N));
}
__device__ __forceinline__ unsigned h2_as_u32(__half2 h) {
    return *reinterpret_cast<unsigned*>(&h);
}
__device__ __forceinline__ uint32_t smem_u32(const void* p) {
    return (uint32_t)__cvta_generic_to_shared(p);
}
__device__ __forceinline__ void ldsm_x4(unsigned& r0, unsigned& r1, unsigned& r2, unsigned& r3,
                                        uint32_t addr) {
    asm volatile("ldmatrix.sync.aligned.m8n8.x4.shared.b16 {%0,%1,%2,%3}, [%4];"
                 : "=r"(r0), "=r"(r1), "=r"(r2), "=r"(r3) : "r"(addr));
}
__device__ __forceinline__ void mma_f16(float* d, const unsigned* a, unsigned b0, unsigned b1) {
    asm volatile(
        "mma.sync.aligned.m16n8k16.row.col.f32.f16.f16.f32 "
        "{%0,%1,%2,%3},{%4,%5,%6,%7},{%8,%9},{%0,%1,%2,%3};\n"
        : "+f"(d[0]),"+f"(d[1]),"+f"(d[2]),"+f"(d[3])
        : "r"(a[0]),"r"(a[1]),"r"(a[2]),"r"(a[3]),"r"(b0),"r"(b1));
}

// ============================================================
// fp32 -> fp16 conversion prepass (grid-stride float4)
// ============================================================
__global__ void f32_to_f16_kernel(const float4* __restrict__ src, uint2* __restrict__ dst, int n4)
{
    for (int i = blockIdx.x*blockDim.x + threadIdx.x; i < n4; i += gridDim.x*blockDim.x) {
        float4 v = src[i];
        uint2 o;
        o.x = h2_as_u32(__floats2half2_rn(v.x, v.y));
        o.y = h2_as_u32(__floats2half2_rn(v.z, v.w));
        dst[i] = o;
    }
}

// ============================================================
// fp16 mma GEMM:  C[M,N] = A[M,1024] * W[N,1024]^T + bias[N]
// CTA tile 128x128, BK=64, 256 thr = 8 warps, warp tile 32x64.
// ldmatrix.x4 fragment loads from XOR-swizzled 128B-row smem.
// MODE 0: A=g_xh,  W=g_wqkvh -> writes Q(x0.125)/K/V fp16 scratch [B,H,T,dk]
// MODE 1: A=g_ctxh, W=g_wouth -> writes Cout[M,DM] fp32 (+bias)
// ============================================================
#define GEMM_SMEM (4*16384)   // 2 x (A 16KB) + 2 x (B 16KB)

template<int MODE>
__global__ __launch_bounds__(256, 2)
void gemm_f16_kernel(const float* __restrict__ bias, float* __restrict__ Cout)
{
    extern __shared__ char smraw[];
    const uint32_t sa = smem_u32(smraw);            // A buffers
    const uint32_t sb = sa + 2*16384;               // B buffers

    const int tid  = threadIdx.x;
    const int warp = tid >> 5;
    const int lane = tid & 31;
    const int wm   = warp >> 1;      // 0..3
    const int wn   = warp & 1;       // 0..1
    const int bm   = blockIdx.y;
    const int bn   = blockIdx.x;

    const __half* Ab = (MODE == 0 ? g_xh : g_ctxh) + (size_t)(bm*128)*1024;
    const __half* Wb = (MODE == 0 ? g_wqkvh : g_wouth) + (size_t)(bn*128)*1024;

    float acc[2][8][4];
    #pragma unroll
    for (int x=0;x<2;x++)
        #pragma unroll
        for (int j=0;j<8;j++)
            #pragma unroll
            for (int e=0;e<4;e++) acc[x][j][e] = 0.0f;

    auto preload = [&](int ci) {
        const int st = ci & 1;
        const uint32_t ab = sa + st*16384;
        const uint32_t bb = sb + st*16384;
        #pragma unroll
        for (int it = 0; it < 8; it++) {
            int s = tid + it*256;                   // 0..2047
            if (s < 1024) {                          // A: 128 rows x 8 segs(16B)
                int row = s >> 3, seg = s & 7;
                cp_async16(ab + row*128 + ((seg*16) ^ ((row&7)*16)),
                           Ab + (size_t)row*1024 + ci*64 + seg*8);
            } else {                                 // B: 128 rows x 8 segs
                int q = s - 1024;
                int row = q >> 3, seg = q & 7;
                cp_async16(bb + row*128 + ((seg*16) ^ ((row&7)*16)),
                           Wb + (size_t)row*1024 + ci*64 + seg*8);
            }
        }
    };

    preload(0); cp_commit();
    preload(1); cp_commit();

    for (int i = 0; i < 16; i++) {
        if (i < 15) cp_wait<1>(); else cp_wait<0>();
        __syncthreads();
        const uint32_t ab = sa + (i&1)*16384;
        const uint32_t bb = sb + (i&1)*16384;

        #pragma unroll
        for (int ks = 0; ks < 4; ks++) {
            unsigned af[2][4];
            #pragma unroll
            for (int x = 0; x < 2; x++) {
                int lrow = wm*32 + x*16 + (lane & 15);
                int kb   = ks*32 + (lane >> 4)*16;
                ldsm_x4(af[x][0], af[x][1], af[x][2], af[x][3],
                        ab + lrow*128 + (kb ^ ((lrow&7)*16)));
            }
            #pragma unroll
            for (int jj = 0; jj < 4; jj++) {
                int nrow = wn*64 + jj*16 + (lane & 7) + (lane >> 4)*8;
                int kb   = ks*32 + ((lane >> 3) & 1)*16;
                unsigned b0,b1,b2,b3;
                ldsm_x4(b0, b1, b2, b3, bb + nrow*128 + (kb ^ ((nrow&7)*16)));
                #pragma unroll
                for (int x = 0; x < 2; x++) {
                    mma_f16(acc[x][2*jj  ], af[x], b0, b1);
                    mma_f16(acc[x][2*jj+1], af[x], b2, b3);
                }
            }
        }
        __syncthreads();
        if (i + 2 < 16) { preload(i+2); cp_commit(); }
    }
    __syncthreads();   // all fragment reads done before stage overlays smem

    // ---- epilogue via per-warp smem staging ----
    float* stage = (float*)smraw + warp*16*20;
    const int r = lane >> 2, c = lane & 3;
    #pragma unroll
    for (int x = 0; x < 2; x++) {
        #pragma unroll
        for (int jj = 0; jj < 4; jj++) {
            stage[ r    *20 + 2*c    ] = acc[x][2*jj][0];
            stage[ r    *20 + 2*c + 1] = acc[x][2*jj][1];
            stage[(r+8) *20 + 2*c    ] = acc[x][2*jj][2];
            stage[(r+8) *20 + 2*c + 1] = acc[x][2*jj][3];
            stage[ r    *20 + 8 + 2*c    ] = acc[x][2*jj+1][0];
            stage[ r    *20 + 8 + 2*c + 1] = acc[x][2*jj+1][1];
            stage[(r+8) *20 + 8 + 2*c    ] = acc[x][2*jj+1][2];
            stage[(r+8) *20 + 8 + 2*c + 1] = acc[x][2*jj+1][3];
            __syncwarp();
            #pragma unroll
            for (int e = 0; e < 8; e++) {
                int idx = e*32 + lane;
                int rr = idx >> 4, cc = idx & 15;
                int gm = bm*128 + wm*32 + x*16 + rr;
                int gn = bn*128 + wn*64 + jj*16 + cc;
                float v = stage[rr*20 + cc] + __ldg(&bias[gn]);
                if (MODE == 0) {
                    int b = gm >> 11, t = gm & 2047;
                    int part = gn >> 10, rem = gn & 1023;
                    int h = rem >> 6, d = rem & 63;
                    size_t off = (((size_t)(b*NH + h))*SEQ + t)*DK + d;
                    if (part == 0)      g_Qh[off] = __float2half_rn(v * 0.125f);
                    else if (part == 1) g_Kh[off] = __float2half_rn(v);
                    else                g_Vh[off] = __float2half_rn(v);
                } else {
                    Cout[(size_t)gm*DM + gn] = v;
                }
            }
            __syncwarp();
        }
    }
}

// ============================================================
// FlashAttention-2, all-fp16 operands:
// CTA = (b, h, 128 queries), 8 warps, 16 rows/warp.
// S = Q K^T via mma.m16n8k16.f16 (Q regs from gmem, K LDS half2,
// conflict-free stride-72), softmax in regs, P fp16 in regs,
// O += P V via mma + ldmatrix.trans. O in regs until final store.
// ============================================================
#define KV_LD 72   // halves per K/V row
#define ATTN_SMEM (4*64*KV_LD*2)   // K(2buf) + V(2buf), fp16

__global__ __launch_bounds__(256, 2)
void attn_kernel()
{
    extern __shared__ char smraw[];
    __half* Ksm = (__half*)smraw;                 // 2 x 64 x 72
    __half* Vsm = Ksm + 2*64*KV_LD;               // 2 x 64 x 72

    const int tid  = threadIdx.x;
    const int warp = tid >> 5;
    const int lane = tid & 31;
    const int r    = lane >> 2;      // 0..7
    const int c    = lane & 3;       // 0..3
    const int q0   = blockIdx.x * 128;
    const int h    = blockIdx.y;
    const int b    = blockIdx.z;
    const size_t headbase = ((size_t)(b*NH + h))*SEQ*DK;

    // ---- Q fragments (fp16, pre-scaled) straight from gmem ----
    unsigned qf[4][4];
    {
        const __half* q_r0 = g_Qh + headbase + (size_t)(q0 + warp*16 + r)*DK;
        const __half* q_r1 = q_r0 + 8*DK;
        #pragma unroll
        for (int s = 0; s < 4; s++) {
            qf[s][0] = *(const unsigned*)(q_r0 + 16*s + 2*c);
            qf[s][1] = *(const unsigned*)(q_r1 + 16*s + 2*c);
            qf[s][2] = *(const unsigned*)(q_r0 + 16*s + 2*c + 8);
            qf[s][3] = *(const unsigned*)(q_r1 + 16*s + 2*c + 8);
        }
    }

    float Oacc[8][4];
    #pragma unroll
    for (int j=0;j<8;j++)
        #pragma unroll
        for (int e=0;e<4;e++) Oacc[j][e] = 0.0f;
    float mrow[2] = {-CUDART_INF_F, -CUDART_INF_F};
    float lrow[2] = {0.0f, 0.0f};

    const uint32_t kbase0 = smem_u32(Ksm);
    const uint32_t vbase0 = smem_u32(Vsm);

    auto preload = [&](int kt, int st) {
        const size_t kb = headbase + (size_t)kt*64*DK;
        const uint32_t kd = kbase0 + (uint32_t)(st*64*KV_LD*2);
        const uint32_t vd = vbase0 + (uint32_t)(st*64*KV_LD*2);
        #pragma unroll
        for (int it = 0; it < 2; it++) {             // K: 512 x 16B
            int idx = tid + it*256;
            int row = idx >> 3, seg = idx & 7;
            cp_async16(kd + row*KV_LD*2 + seg*16, g_Kh + kb + (size_t)row*DK + seg*8);
        }
        #pragma unroll
        for (int it = 0; it < 2; it++) {             // V: 512 x 16B
            int idx = tid + it*256;
            int row = idx >> 3, seg = idx & 7;
            cp_async16(vd + row*KV_LD*2 + seg*16, g_Vh + kb + (size_t)row*DK + seg*8);
        }
    };

    preload(0, 0); cp_commit();
    preload(1, 1); cp_commit();

    for (int kt = 0; kt < SEQ/64; kt++) {
        if (kt < SEQ/64 - 1) cp_wait<1>(); else cp_wait<0>();
        __syncthreads();
        const int st = kt & 1;
        const __half* Kst = Ksm + st*64*KV_LD;
        const uint32_t vb = vbase0 + (uint32_t)(st*64*KV_LD*2);

        // ---- S = Q K^T (fp16 mma) ----
        float Sacc[8][4];
        #pragma unroll
        for (int j=0;j<8;j++)
            #pragma unroll
            for (int e=0;e<4;e++) Sacc[j][e] = 0.0f;
        #pragma unroll
        for (int s = 0; s < 4; s++) {
            #pragma unroll
            for (int j = 0; j < 8; j++) {
                const __half* kp = Kst + (8*j + r)*KV_LD + 16*s + 2*c;
                unsigned b0 = *(const unsigned*)kp;
                unsigned b1 = *(const unsigned*)(kp + 8);
                mma_f16(Sacc[j], qf[s], b0, b1);
            }
        }

        // ---- online softmax in registers ----
        float mx0 = Sacc[0][0], mx1 = Sacc[0][2];
        #pragma unroll
        for (int j=0;j<8;j++) {
            mx0 = fmaxf(mx0, fmaxf(Sacc[j][0], Sacc[j][1]));
            mx1 = fmaxf(mx1, fmaxf(Sacc[j][2], Sacc[j][3]));
        }
        mx0 = fmaxf(mx0, __shfl_xor_sync(0xffffffffu, mx0, 1));
        mx0 = fmaxf(mx0, __shfl_xor_sync(0xffffffffu, mx0, 2));
        mx1 = fmaxf(mx1, __shfl_xor_sync(0xffffffffu, mx1, 1));
        mx1 = fmaxf(mx1, __shfl_xor_sync(0xffffffffu, mx1, 2));
        float mn0 = fmaxf(mrow[0], mx0), mn1 = fmaxf(mrow[1], mx1);
        float al0 = __expf(mrow[0] - mn0), al1 = __expf(mrow[1] - mn1);
        mrow[0] = mn0; mrow[1] = mn1;

        unsigned ph[16];
        float sum0 = 0.0f, sum1 = 0.0f;
        #pragma unroll
        for (int j = 0; j < 8; j++) {
            float p0 = __expf(Sacc[j][0] - mn0);
            float p1 = __expf(Sacc[j][1] - mn0);
            float p2 = __expf(Sacc[j][2] - mn1);
            float p3 = __expf(Sacc[j][3] - mn1);
            sum0 += p0 + p1; sum1 += p2 + p3;
            ph[2*j  ] = h2_as_u32(__floats2half2_rn(p0, p1));
            ph[2*j+1] = h2_as_u32(__floats2half2_rn(p2, p3));
        }
        sum0 += __shfl_xor_sync(0xffffffffu, sum0, 1);
        sum0 += __shfl_xor_sync(0xffffffffu, sum0, 2);
        sum1 += __shfl_xor_sync(0xffffffffu, sum1, 1);
        sum1 += __shfl_xor_sync(0xffffffffu, sum1, 2);
        lrow[0] = lrow[0]*al0 + sum0;
        lrow[1] = lrow[1]*al1 + sum1;
        #pragma unroll
        for (int j=0;j<8;j++) {
            Oacc[j][0] *= al0; Oacc[j][1] *= al0;
            Oacc[j][2] *= al1; Oacc[j][3] *= al1;
        }

        // ---- O += P V (fp16 mma, V via ldmatrix.trans) ----
        const int t  = lane >> 3;
        const int rr = lane & 7;
        #pragma unroll
        for (int s = 0; s < 4; s++) {
            const unsigned* af = &ph[4*s];
            #pragma unroll
            for (int g = 0; g < 4; g++) {
                uint32_t addr = vb + (uint32_t)(((16*s + (t&1)*8 + rr)*KV_LD + (t>>1)*8 + g*16)*2);
                unsigned r0,r1,r2,r3;
                asm volatile(
                    "ldmatrix.sync.aligned.m8n8.x4.trans.shared.b16 {%0,%1,%2,%3}, [%4];\n"
                    : "=r"(r0),"=r"(r1),"=r"(r2),"=r"(r3) : "r"(addr));
                mma_f16(Oacc[2*g  ], af, r0, r1);
                mma_f16(Oacc[2*g+1], af, r2, r3);
            }
        }

        __syncthreads();
        if (kt + 2 < SEQ/64) { preload(kt+2, st); cp_commit(); }
    }

    // ---- normalize + write ctx fp16 [B,T,DM] ----
    {
        float inv0 = 1.0f / lrow[0];
        float inv1 = 1.0f / lrow[1];
        __half* row0 = g_ctxh + ((size_t)(b*SEQ + q0 + warp*16 + r    ))*DM + h*DK;
        __half* row1 = g_ctxh + ((size_t)(b*SEQ + q0 + warp*16 + r + 8))*DM + h*DK;
        #pragma unroll
        for (int j = 0; j < 8; j++) {
            *(__half2*)(row0 + 8*j + 2*c) = __floats2half2_rn(Oacc[j][0]*inv0, Oacc[j][1]*inv0);
            *(__half2*)(row1 + 8*j + 2*c) = __floats2half2_rn(Oacc[j][2]*inv1, Oacc[j][3]*inv1);
        }
    }
}

// ============================================================
extern "C" void kernel_launch(void* const* d_in, const int* in_sizes, int n_in,
                              void* d_out, int out_size)
{
    (void)in_sizes; (void)n_in; (void)out_size;
    const float* x     = (const float*)d_in[0];
    const float* w_qkv = (const float*)d_in[1];
    const float* b_qkv = (const float*)d_in[2];
    const float* w_out = (const float*)d_in[3];
    const float* b_out = (const float*)d_in[4];
    float* out = (float*)d_out;

    cudaFuncSetAttribute(gemm_f16_kernel<0>, cudaFuncAttributeMaxDynamicSharedMemorySize, GEMM_SMEM);
    cudaFuncSetAttribute(gemm_f16_kernel<1>, cudaFuncAttributeMaxDynamicSharedMemorySize, GEMM_SMEM);
    cudaFuncSetAttribute(attn_kernel, cudaFuncAttributeMaxDynamicSharedMemorySize, ATTN_SMEM);

    void *xh, *wqkvh, *wouth;
    cudaGetSymbolAddress(&xh,    g_xh);
    cudaGetSymbolAddress(&wqkvh, g_wqkvh);
    cudaGetSymbolAddress(&wouth, g_wouth);

    // 0) fp32 -> fp16 conversion prepass (round-to-nearest)
    f32_to_f16_kernel<<<512, 256>>>((const float4*)x,     (uint2*)xh,    (M_TOT*DM)/4);
    f32_to_f16_kernel<<<512, 256>>>((const float4*)w_qkv, (uint2*)wqkvh, (3*DM*DM)/4);
    f32_to_f16_kernel<<<512, 256>>>((const float4*)w_out, (uint2*)wouth, (DM*DM)/4);

    // 1) QKV projection (fp16 mma) -> Q/K/V fp16 scratch
    gemm_f16_kernel<0><<<dim3(3*DM/128, M_TOT/128), 256, GEMM_SMEM>>>(b_qkv, nullptr);
    // 2) attention -> ctx fp16 scratch
    attn_kernel<<<dim3(SEQ/128, NH, BATCH), 256, ATTN_SMEM>>>();
    // 3) output projection (fp16 mma) -> d_out fp32
    gemm_f16_kernel<1><<<dim3(DM/128, M_TOT/128), 256, GEMM_SMEM>>>(b_out, out);
}

// round 9
// speedup vs baseline: 6.8607x; 1.0567x over previous
#include <cuda_runtime.h>
#include <cuda_fp16.h>
#include <math_constants.h>
#include <cstdint>

#define BATCH 2
#define SEQ   2048
#define DM    1024
#define NH    16
#define DK    64
#define M_TOT (BATCH*SEQ)   // 4096

// -------- scratch (device globals: allocation-free) --------
__device__ __half g_Qh [(size_t)BATCH*NH*SEQ*DK];   // pre-scaled by 0.125*log2(e)
__device__ __half g_Kh [(size_t)BATCH*NH*SEQ*DK];
__device__ __half g_Vh [(size_t)BATCH*NH*SEQ*DK];
__device__ __half g_ctxh[(size_t)M_TOT*DM];
__device__ __half g_xh   [(size_t)M_TOT*DM];
__device__ __half g_wqkvh[(size_t)3*DM*DM];
__device__ __half g_wouth[(size_t)DM*DM];

// -------- helpers --------
__device__ __forceinline__ void cp_async16(uint32_t smem, const void* gmem) {
    asm volatile("cp.async.cg.shared.global [%0], [%1], 16;\n" :: "r"(smem), "l"(gmem));
}
__device__ __forceinline__ void cp_commit() { asm volatile("cp.async.commit_group;\n"); }
template<int N> __device__ __forceinline__ void cp_wait() {
    asm volatile("cp.async.wait_group %0;\n" :: "n"(N));
}
__device__ __forceinline__ unsigned h2_as_u32(__half2 h) {
    return *reinterpret_cast<unsigned*>(&h);
}
__device__ __forceinline__ uint32_t smem_u32(const void* p) {
    return (uint32_t)__cvta_generic_to_shared(p);
}
__device__ __forceinline__ void ldsm_x4(unsigned& r0, unsigned& r1, unsigned& r2, unsigned& r3,
                                        uint32_t addr) {
    asm volatile("ldmatrix.sync.aligned.m8n8.x4.shared.b16 {%0,%1,%2,%3}, [%4];"
                 : "=r"(r0), "=r"(r1), "=r"(r2), "=r"(r3) : "r"(addr));
}
__device__ __forceinline__ void mma_f16(float* d, const unsigned* a, unsigned b0, unsigned b1) {
    asm volatile(
        "mma.sync.aligned.m16n8k16.row.col.f32.f16.f16.f32 "
        "{%0,%1,%2,%3},{%4,%5,%6,%7},{%8,%9},{%0,%1,%2,%3};\n"
        : "+f"(d[0]),"+f"(d[1]),"+f"(d[2]),"+f"(d[3])
        : "r"(a[0]),"r"(a[1]),"r"(a[2]),"r"(a[3]),"r"(b0),"r"(b1));
}

// ============================================================
// fused fp32 -> fp16 conversion prepass (one launch)
// ============================================================
__global__ void prep_kernel(const float4* __restrict__ x,
                            const float4* __restrict__ wq,
                            const float4* __restrict__ wo,
                            uint2* __restrict__ xh,
                            uint2* __restrict__ wqh,
                            uint2* __restrict__ woh)
{
    const int stride = gridDim.x * blockDim.x;
    const int t0 = blockIdx.x*blockDim.x + threadIdx.x;
    #pragma unroll 1
    for (int i = t0; i < (M_TOT*DM)/4; i += stride) {
        float4 v = x[i];
        xh[i] = make_uint2(h2_as_u32(__floats2half2_rn(v.x, v.y)),
                           h2_as_u32(__floats2half2_rn(v.z, v.w)));
    }
    #pragma unroll 1
    for (int i = t0; i < (3*DM*DM)/4; i += stride) {
        float4 v = wq[i];
        wqh[i] = make_uint2(h2_as_u32(__floats2half2_rn(v.x, v.y)),
                            h2_as_u32(__floats2half2_rn(v.z, v.w)));
    }
    #pragma unroll 1
    for (int i = t0; i < (DM*DM)/4; i += stride) {
        float4 v = wo[i];
        woh[i] = make_uint2(h2_as_u32(__floats2half2_rn(v.x, v.y)),
                            h2_as_u32(__floats2half2_rn(v.z, v.w)));
    }
}

// ============================================================
// fp16 mma GEMM:  C[M,N] = A[M,1024] * W[N,1024]^T + bias[N]
// CTA 128x128, BK=64, 8 warps, warp tile 32x64. 3-stage cp.async
// pipeline, ONE __syncthreads per iteration:
//   wait<1> ; sync ; prefetch(i+2) ; compute(i%3)
// MODE 0 -> Q(x0.125*log2e)/K/V fp16 scratch; MODE 1 -> fp32 out.
// ============================================================
#define GSTG 16384
#define GEMM_SMEM (6*GSTG)   // 3 x A(16KB) + 3 x B(16KB)

template<int MODE>
__global__ __launch_bounds__(256, 2)
void gemm_f16_kernel(const float* __restrict__ bias, float* __restrict__ Cout)
{
    extern __shared__ char smraw[];
    const uint32_t sa = smem_u32(smraw);            // A stages [0,3)
    const uint32_t sb = sa + 3*GSTG;                // B stages [0,3)

    const int tid  = threadIdx.x;
    const int warp = tid >> 5;
    const int lane = tid & 31;
    const int wm   = warp >> 1;      // 0..3
    const int wn   = warp & 1;       // 0..1
    const int bm   = blockIdx.y;
    const int bn   = blockIdx.x;

    const __half* Ab = (MODE == 0 ? g_xh : g_ctxh) + (size_t)(bm*128)*1024;
    const __half* Wb = (MODE == 0 ? g_wqkvh : g_wouth) + (size_t)(bn*128)*1024;

    float acc[2][8][4];
    #pragma unroll
    for (int x=0;x<2;x++)
        #pragma unroll
        for (int j=0;j<8;j++)
            #pragma unroll
            for (int e=0;e<4;e++) acc[x][j][e] = 0.0f;

    auto preload = [&](int ci) {
        const int st = ci % 3;
        const uint32_t ab = sa + st*GSTG;
        const uint32_t bb = sb + st*GSTG;
        #pragma unroll
        for (int it = 0; it < 8; it++) {
            int s = tid + it*256;                   // 0..2047
            if (s < 1024) {                          // A: 128 rows x 8 segs(16B)
                int row = s >> 3, seg = s & 7;
                cp_async16(ab + row*128 + ((seg*16) ^ ((row&7)*16)),
                           Ab + (size_t)row*1024 + ci*64 + seg*8);
            } else {                                 // B
                int q = s - 1024;
                int row = q >> 3, seg = q & 7;
                cp_async16(bb + row*128 + ((seg*16) ^ ((row&7)*16)),
                           Wb + (size_t)row*1024 + ci*64 + seg*8);
            }
        }
    };

    preload(0); cp_commit();
    preload(1); cp_commit();

    for (int i = 0; i < 16; i++) {
        if (i < 15) cp_wait<1>(); else cp_wait<0>();
        __syncthreads();
        if (i + 2 < 16) { preload(i+2); cp_commit(); }

        const uint32_t ab = sa + (i%3)*GSTG;
        const uint32_t bb = sb + (i%3)*GSTG;
        #pragma unroll
        for (int ks = 0; ks < 4; ks++) {
            unsigned af[2][4];
            #pragma unroll
            for (int x = 0; x < 2; x++) {
                int lrow = wm*32 + x*16 + (lane & 15);
                int kb   = ks*32 + (lane >> 4)*16;
                ldsm_x4(af[x][0], af[x][1], af[x][2], af[x][3],
                        ab + lrow*128 + (kb ^ ((lrow&7)*16)));
            }
            #pragma unroll
            for (int jj = 0; jj < 4; jj++) {
                int nrow = wn*64 + jj*16 + (lane & 7) + (lane >> 4)*8;
                int kb   = ks*32 + ((lane >> 3) & 1)*16;
                unsigned b0,b1,b2,b3;
                ldsm_x4(b0, b1, b2, b3, bb + nrow*128 + (kb ^ ((nrow&7)*16)));
                #pragma unroll
                for (int x = 0; x < 2; x++) {
                    mma_f16(acc[x][2*jj  ], af[x], b0, b1);
                    mma_f16(acc[x][2*jj+1], af[x], b2, b3);
                }
            }
        }
    }
    __syncthreads();   // all fragment reads done before stage overlays smem

    // ---- epilogue via per-warp smem staging ----
    float* stage = (float*)smraw + warp*16*20;
    const int r = lane >> 2, c = lane & 3;
    #pragma unroll
    for (int x = 0; x < 2; x++) {
        #pragma unroll
        for (int jj = 0; jj < 4; jj++) {
            stage[ r    *20 + 2*c    ] = acc[x][2*jj][0];
            stage[ r    *20 + 2*c + 1] = acc[x][2*jj][1];
            stage[(r+8) *20 + 2*c    ] = acc[x][2*jj][2];
            stage[(r+8) *20 + 2*c + 1] = acc[x][2*jj][3];
            stage[ r    *20 + 8 + 2*c    ] = acc[x][2*jj+1][0];
            stage[ r    *20 + 8 + 2*c + 1] = acc[x][2*jj+1][1];
            stage[(r+8) *20 + 8 + 2*c    ] = acc[x][2*jj+1][2];
            stage[(r+8) *20 + 8 + 2*c + 1] = acc[x][2*jj+1][3];
            __syncwarp();
            #pragma unroll
            for (int e = 0; e < 8; e++) {
                int idx = e*32 + lane;
                int rr = idx >> 4, cc = idx & 15;
                int gm = bm*128 + wm*32 + x*16 + rr;
                int gn = bn*128 + wn*64 + jj*16 + cc;
                float v = stage[rr*20 + cc] + __ldg(&bias[gn]);
                if (MODE == 0) {
                    int b = gm >> 11, t = gm & 2047;
                    int part = gn >> 10, rem = gn & 1023;
                    int h = rem >> 6, d = rem & 63;
                    size_t off = (((size_t)(b*NH + h))*SEQ + t)*DK + d;
                    if (part == 0)      g_Qh[off] = __float2half_rn(v * 0.1803368801f); // 0.125*log2(e)
                    else if (part == 1) g_Kh[off] = __float2half_rn(v);
                    else                g_Vh[off] = __float2half_rn(v);
                } else {
                    Cout[(size_t)gm*DM + gn] = v;
                }
            }
            __syncwarp();
        }
    }
}

// ============================================================
// FlashAttention-2, all-fp16:
// CTA = (b, h, 128 queries), 8 warps, 16 rows/warp. 3-stage KV
// pipeline, one sync/iter. S = Q K^T with K B-fragments via
// ldmatrix.x4 (one LDSM covers two j-tiles). Softmax in base-2
// (log2e folded into Q). P fp16 regs; O += P V via ldmatrix.trans.
// ============================================================
#define KV_LD 72                       // halves per K/V row
#define KVBUF (64*KV_LD)               // halves per stage
#define ATTN_SMEM (6*KVBUF*2)          // 3 x K + 3 x V

__global__ __launch_bounds__(256, 2)
void attn_kernel()
{
    extern __shared__ char smraw[];
    __half* Ksm = (__half*)smraw;                 // 3 x 64 x 72
    __half* Vsm = Ksm + 3*KVBUF;                  // 3 x 64 x 72

    const int tid  = threadIdx.x;
    const int warp = tid >> 5;
    const int lane = tid & 31;
    const int r    = lane >> 2;      // 0..7
    const int c    = lane & 3;       // 0..3
    const int q0   = blockIdx.x * 128;
    const int h    = blockIdx.y;
    const int b    = blockIdx.z;
    const size_t headbase = ((size_t)(b*NH + h))*SEQ*DK;

    // ---- Q fragments (fp16, pre-scaled incl. log2e) from gmem ----
    unsigned qf[4][4];
    {
        const __half* q_r0 = g_Qh + headbase + (size_t)(q0 + warp*16 + r)*DK;
        const __half* q_r1 = q_r0 + 8*DK;
        #pragma unroll
        for (int s = 0; s < 4; s++) {
            qf[s][0] = *(const unsigned*)(q_r0 + 16*s + 2*c);
            qf[s][1] = *(const unsigned*)(q_r1 + 16*s + 2*c);
            qf[s][2] = *(const unsigned*)(q_r0 + 16*s + 2*c + 8);
            qf[s][3] = *(const unsigned*)(q_r1 + 16*s + 2*c + 8);
        }
    }

    float Oacc[8][4];
    #pragma unroll
    for (int j=0;j<8;j++)
        #pragma unroll
        for (int e=0;e<4;e++) Oacc[j][e] = 0.0f;
    float mrow[2] = {-CUDART_INF_F, -CUDART_INF_F};
    float lrow[2] = {0.0f, 0.0f};

    const uint32_t kbase0 = smem_u32(Ksm);
    const uint32_t vbase0 = smem_u32(Vsm);

    auto preload = [&](int kt) {
        const int st = kt % 3;
        const size_t kb = headbase + (size_t)kt*64*DK;
        const uint32_t kd = kbase0 + (uint32_t)(st*KVBUF*2);
        const uint32_t vd = vbase0 + (uint32_t)(st*KVBUF*2);
        #pragma unroll
        for (int it = 0; it < 2; it++) {             // K: 512 x 16B
            int idx = tid + it*256;
            int row = idx >> 3, seg = idx & 7;
            cp_async16(kd + row*KV_LD*2 + seg*16, g_Kh + kb + (size_t)row*DK + seg*8);
        }
        #pragma unroll
        for (int it = 0; it < 2; it++) {             // V: 512 x 16B
            int idx = tid + it*256;
            int row = idx >> 3, seg = idx & 7;
            cp_async16(vd + row*KV_LD*2 + seg*16, g_Vh + kb + (size_t)row*DK + seg*8);
        }
    };

    preload(0); cp_commit();
    preload(1); cp_commit();

    for (int kt = 0; kt < SEQ/64; kt++) {
        if (kt < SEQ/64 - 1) cp_wait<1>(); else cp_wait<0>();
        __syncthreads();
        if (kt + 2 < SEQ/64) { preload(kt+2); cp_commit(); }

        const int st = kt % 3;
        const uint32_t kb32 = kbase0 + (uint32_t)(st*KVBUF*2);
        const uint32_t vb   = vbase0 + (uint32_t)(st*KVBUF*2);

        // ---- S = Q K^T (fp16 mma, K B-fragments via ldmatrix.x4) ----
        float Sacc[8][4];
        #pragma unroll
        for (int j=0;j<8;j++)
            #pragma unroll
            for (int e=0;e<4;e++) Sacc[j][e] = 0.0f;
        const int n_off = ((lane >> 4) << 3) + (lane & 7);   // (group>>1)*8 + row
        const int c_off = ((lane >> 3) & 1) << 3;            // (group&1)*8
        #pragma unroll
        for (int s = 0; s < 4; s++) {
            #pragma unroll
            for (int jp = 0; jp < 4; jp++) {
                uint32_t addr = kb32 + (uint32_t)((((16*jp + n_off)*KV_LD) + 16*s + c_off)*2);
                unsigned b0,b1,b2,b3;
                ldsm_x4(b0, b1, b2, b3, addr);
                mma_f16(Sacc[2*jp  ], qf[s], b0, b1);
                mma_f16(Sacc[2*jp+1], qf[s], b2, b3);
            }
        }

        // ---- online softmax (base-2) in registers ----
        float mx0 = Sacc[0][0], mx1 = Sacc[0][2];
        #pragma unroll
        for (int j=0;j<8;j++) {
            mx0 = fmaxf(mx0, fmaxf(Sacc[j][0], Sacc[j][1]));
            mx1 = fmaxf(mx1, fmaxf(Sacc[j][2], Sacc[j][3]));
        }
        mx0 = fmaxf(mx0, __shfl_xor_sync(0xffffffffu, mx0, 1));
        mx0 = fmaxf(mx0, __shfl_xor_sync(0xffffffffu, mx0, 2));
        mx1 = fmaxf(mx1, __shfl_xor_sync(0xffffffffu, mx1, 1));
        mx1 = fmaxf(mx1, __shfl_xor_sync(0xffffffffu, mx1, 2));
        float mn0 = fmaxf(mrow[0], mx0), mn1 = fmaxf(mrow[1], mx1);
        float al0 = exp2f(mrow[0] - mn0), al1 = exp2f(mrow[1] - mn1);
        mrow[0] = mn0; mrow[1] = mn1;

        unsigned ph[16];
        float sum0 = 0.0f, sum1 = 0.0f;
        #pragma unroll
        for (int j = 0; j < 8; j++) {
            float p0 = exp2f(Sacc[j][0] - mn0);
            float p1 = exp2f(Sacc[j][1] - mn0);
            float p2 = exp2f(Sacc[j][2] - mn1);
            float p3 = exp2f(Sacc[j][3] - mn1);
            sum0 += p0 + p1; sum1 += p2 + p3;
            ph[2*j  ] = h2_as_u32(__floats2half2_rn(p0, p1));
            ph[2*j+1] = h2_as_u32(__floats2half2_rn(p2, p3));
        }
        sum0 += __shfl_xor_sync(0xffffffffu, sum0, 1);
        sum0 += __shfl_xor_sync(0xffffffffu, sum0, 2);
        sum1 += __shfl_xor_sync(0xffffffffu, sum1, 1);
        sum1 += __shfl_xor_sync(0xffffffffu, sum1, 2);
        lrow[0] = lrow[0]*al0 + sum0;
        lrow[1] = lrow[1]*al1 + sum1;
        #pragma unroll
        for (int j=0;j<8;j++) {
            Oacc[j][0] *= al0; Oacc[j][1] *= al0;
            Oacc[j][2] *= al1; Oacc[j][3] *= al1;
        }

        // ---- O += P V (fp16 mma, V via ldmatrix.trans) ----
        const int t  = lane >> 3;
        const int rr = lane & 7;
        #pragma unroll
        for (int s = 0; s < 4; s++) {
            const unsigned* af = &ph[4*s];
            #pragma unroll
            for (int g = 0; g < 4; g++) {
                uint32_t addr = vb + (uint32_t)(((16*s + (t&1)*8 + rr)*KV_LD + (t>>1)*8 + g*16)*2);
                unsigned r0,r1,r2,r3;
                asm volatile(
                    "ldmatrix.sync.aligned.m8n8.x4.trans.shared.b16 {%0,%1,%2,%3}, [%4];\n"
                    : "=r"(r0),"=r"(r1),"=r"(r2),"=r"(r3) : "r"(addr));
                mma_f16(Oacc[2*g  ], af, r0, r1);
                mma_f16(Oacc[2*g+1], af, r2, r3);
            }
        }
    }

    // ---- normalize + write ctx fp16 [B,T,DM] ----
    {
        float inv0 = 1.0f / lrow[0];
        float inv1 = 1.0f / lrow[1];
        __half* row0 = g_ctxh + ((size_t)(b*SEQ + q0 + warp*16 + r    ))*DM + h*DK;
        __half* row1 = g_ctxh + ((size_t)(b*SEQ + q0 + warp*16 + r + 8))*DM + h*DK;
        #pragma unroll
        for (int j = 0; j < 8; j++) {
            *(__half2*)(row0 + 8*j + 2*c) = __floats2half2_rn(Oacc[j][0]*inv0, Oacc[j][1]*inv0);
            *(__half2*)(row1 + 8*j + 2*c) = __floats2half2_rn(Oacc[j][2]*inv1, Oacc[j][3]*inv1);
        }
    }
}

// ============================================================
extern "C" void kernel_launch(void* const* d_in, const int* in_sizes, int n_in,
                              void* d_out, int out_size)
{
    (void)in_sizes; (void)n_in; (void)out_size;
    const float* x     = (const float*)d_in[0];
    const float* w_qkv = (const float*)d_in[1];
    const float* b_qkv = (const float*)d_in[2];
    const float* w_out = (const float*)d_in[3];
    const float* b_out = (const float*)d_in[4];
    float* out = (float*)d_out;

    cudaFuncSetAttribute(gemm_f16_kernel<0>, cudaFuncAttributeMaxDynamicSharedMemorySize, GEMM_SMEM);
    cudaFuncSetAttribute(gemm_f16_kernel<1>, cudaFuncAttributeMaxDynamicSharedMemorySize, GEMM_SMEM);
    cudaFuncSetAttribute(attn_kernel, cudaFuncAttributeMaxDynamicSharedMemorySize, ATTN_SMEM);

    void *xh, *wqkvh, *wouth;
    cudaGetSymbolAddress(&xh,    g_xh);
    cudaGetSymbolAddress(&wqkvh, g_wqkvh);
    cudaGetSymbolAddress(&wouth, g_wouth);

    // 0) fused fp32 -> fp16 prepass (one launch)
    prep_kernel<<<1024, 256>>>((const float4*)x, (const float4*)w_qkv, (const float4*)w_out,
                               (uint2*)xh, (uint2*)wqkvh, (uint2*)wouth);

    // 1) QKV projection -> Q/K/V fp16 scratch
    gemm_f16_kernel<0><<<dim3(3*DM/128, M_TOT/128), 256, GEMM_SMEM>>>(b_qkv, nullptr);
    // 2) attention -> ctx fp16 scratch
    attn_kernel<<<dim3(SEQ/128, NH, BATCH), 256, ATTN_SMEM>>>();
    // 3) output projection -> d_out fp32
    gemm_f16_kernel<1><<<dim3(DM/128, M_TOT/128), 256, GEMM_SMEM>>>(b_out, out);
}

// round 10
// speedup vs baseline: 7.0155x; 1.0226x over previous
#include <cuda_runtime.h>
#include <cuda_fp16.h>
#include <math_constants.h>
#include <cstdint>

#define BATCH 2
#define SEQ   2048
#define DM    1024
#define NH    16
#define DK    64
#define M_TOT (BATCH*SEQ)   // 4096

// -------- scratch (device globals: allocation-free) --------
__device__ __half g_Qh [(size_t)BATCH*NH*SEQ*DK];   // pre-scaled by 0.125*log2(e)
__device__ __half g_Kh [(size_t)BATCH*NH*SEQ*DK];
__device__ __half g_Vh [(size_t)BATCH*NH*SEQ*DK];
__device__ __half g_ctxh[(size_t)M_TOT*DM];
__device__ __half g_xh   [(size_t)M_TOT*DM];
__device__ __half g_wqkvh[(size_t)3*DM*DM];
__device__ __half g_wouth[(size_t)DM*DM];

// -------- helpers --------
__device__ __forceinline__ void cp_async16(uint32_t smem, const void* gmem) {
    asm volatile("cp.async.cg.shared.global [%0], [%1], 16;\n" :: "r"(smem), "l"(gmem));
}
__device__ __forceinline__ void cp_commit() { asm volatile("cp.async.commit_group;\n"); }
template<int N> __device__ __forceinline__ void cp_wait() {
    asm volatile("cp.async.wait_group %0;\n" :: "n"(N));
}
__device__ __forceinline__ unsigned h2_as_u32(__half2 h) {
    return *reinterpret_cast<unsigned*>(&h);
}
__device__ __forceinline__ uint32_t smem_u32(const void* p) {
    return (uint32_t)__cvta_generic_to_shared(p);
}
__device__ __forceinline__ void ldsm_x4(unsigned& r0, unsigned& r1, unsigned& r2, unsigned& r3,
                                        uint32_t addr) {
    asm volatile("ldmatrix.sync.aligned.m8n8.x4.shared.b16 {%0,%1,%2,%3}, [%4];"
                 : "=r"(r0), "=r"(r1), "=r"(r2), "=r"(r3) : "r"(addr));
}
__device__ __forceinline__ void mma_f16(float* d, const unsigned* a, unsigned b0, unsigned b1) {
    asm volatile(
        "mma.sync.aligned.m16n8k16.row.col.f32.f16.f16.f32 "
        "{%0,%1,%2,%3},{%4,%5,%6,%7},{%8,%9},{%0,%1,%2,%3};\n"
        : "+f"(d[0]),"+f"(d[1]),"+f"(d[2]),"+f"(d[3])
        : "r"(a[0]),"r"(a[1]),"r"(a[2]),"r"(a[3]),"r"(b0),"r"(b1));
}

// ============================================================
// fused fp32 -> fp16 conversion prepass (one launch)
// ============================================================
__global__ void prep_kernel(const float4* __restrict__ x,
                            const float4* __restrict__ wq,
                            const float4* __restrict__ wo,
                            uint2* __restrict__ xh,
                            uint2* __restrict__ wqh,
                            uint2* __restrict__ woh)
{
    const int stride = gridDim.x * blockDim.x;
    const int t0 = blockIdx.x*blockDim.x + threadIdx.x;
    #pragma unroll 1
    for (int i = t0; i < (M_TOT*DM)/4; i += stride) {
        float4 v = x[i];
        xh[i] = make_uint2(h2_as_u32(__floats2half2_rn(v.x, v.y)),
                           h2_as_u32(__floats2half2_rn(v.z, v.w)));
    }
    #pragma unroll 1
    for (int i = t0; i < (3*DM*DM)/4; i += stride) {
        float4 v = wq[i];
        wqh[i] = make_uint2(h2_as_u32(__floats2half2_rn(v.x, v.y)),
                            h2_as_u32(__floats2half2_rn(v.z, v.w)));
    }
    #pragma unroll 1
    for (int i = t0; i < (DM*DM)/4; i += stride) {
        float4 v = wo[i];
        woh[i] = make_uint2(h2_as_u32(__floats2half2_rn(v.x, v.y)),
                            h2_as_u32(__floats2half2_rn(v.z, v.w)));
    }
}

// ============================================================
// fp16 mma GEMM:  C[M,N] = A[M,1024] * W[N,1024]^T + bias[N]
// CTA 128x128, BK=64, 8 warps, warp tile 32x64. 3-stage cp.async
// pipeline, one __syncthreads per iteration. The cp.async
// prefetch burst is issued AFTER the first k-step's LDSM+mma so
// the tensor pipe restarts immediately after the barrier.
// MODE 0 -> Q(x0.125*log2e)/K/V fp16 scratch; MODE 1 -> fp32 out.
// ============================================================
#define GSTG 16384
#define GEMM_SMEM (6*GSTG)   // 3 x A(16KB) + 3 x B(16KB)

template<int MODE>
__global__ __launch_bounds__(256, 2)
void gemm_f16_kernel(const float* __restrict__ bias, float* __restrict__ Cout)
{
    extern __shared__ char smraw[];
    const uint32_t sa = smem_u32(smraw);            // A stages [0,3)
    const uint32_t sb = sa + 3*GSTG;                // B stages [0,3)

    const int tid  = threadIdx.x;
    const int warp = tid >> 5;
    const int lane = tid & 31;
    const int wm   = warp >> 1;      // 0..3
    const int wn   = warp & 1;       // 0..1
    const int bm   = blockIdx.y;
    const int bn   = blockIdx.x;

    const __half* Ab = (MODE == 0 ? g_xh : g_ctxh) + (size_t)(bm*128)*1024;
    const __half* Wb = (MODE == 0 ? g_wqkvh : g_wouth) + (size_t)(bn*128)*1024;

    float acc[2][8][4];
    #pragma unroll
    for (int x=0;x<2;x++)
        #pragma unroll
        for (int j=0;j<8;j++)
            #pragma unroll
            for (int e=0;e<4;e++) acc[x][j][e] = 0.0f;

    auto preload = [&](int ci) {
        const int st = ci % 3;
        const uint32_t ab = sa + st*GSTG;
        const uint32_t bb = sb + st*GSTG;
        #pragma unroll
        for (int it = 0; it < 8; it++) {
            int s = tid + it*256;                   // 0..2047
            if (s < 1024) {                          // A: 128 rows x 8 segs(16B)
                int row = s >> 3, seg = s & 7;
                cp_async16(ab + row*128 + ((seg*16) ^ ((row&7)*16)),
                           Ab + (size_t)row*1024 + ci*64 + seg*8);
            } else {                                 // B
                int q = s - 1024;
                int row = q >> 3, seg = q & 7;
                cp_async16(bb + row*128 + ((seg*16) ^ ((row&7)*16)),
                           Wb + (size_t)row*1024 + ci*64 + seg*8);
            }
        }
    };

    preload(0); cp_commit();
    preload(1); cp_commit();

    for (int i = 0; i < 16; i++) {
        if (i < 15) cp_wait<1>(); else cp_wait<0>();
        __syncthreads();

        const uint32_t ab = sa + (i%3)*GSTG;
        const uint32_t bb = sb + (i%3)*GSTG;

        auto ks_step = [&](int ks) {
            unsigned af[2][4];
            #pragma unroll
            for (int x = 0; x < 2; x++) {
                int lrow = wm*32 + x*16 + (lane & 15);
                int kb   = ks*32 + (lane >> 4)*16;
                ldsm_x4(af[x][0], af[x][1], af[x][2], af[x][3],
                        ab + lrow*128 + (kb ^ ((lrow&7)*16)));
            }
            #pragma unroll
            for (int jj = 0; jj < 4; jj++) {
                int nrow = wn*64 + jj*16 + (lane & 7) + (lane >> 4)*8;
                int kb   = ks*32 + ((lane >> 3) & 1)*16;
                unsigned b0,b1,b2,b3;
                ldsm_x4(b0, b1, b2, b3, bb + nrow*128 + (kb ^ ((nrow&7)*16)));
                #pragma unroll
                for (int x = 0; x < 2; x++) {
                    mma_f16(acc[x][2*jj  ], af[x], b0, b1);
                    mma_f16(acc[x][2*jj+1], af[x], b2, b3);
                }
            }
        };

        // first k-step right after the barrier -> tensor pipe restarts at once
        ks_step(0);
        // prefetch burst overlapped with remaining k-steps
        if (i + 2 < 16) { preload(i+2); cp_commit(); }
        #pragma unroll
        for (int ks = 1; ks < 4; ks++) ks_step(ks);
    }
    __syncthreads();   // all fragment reads done before stage overlays smem

    // ---- epilogue via per-warp smem staging ----
    float* stage = (float*)smraw + warp*16*20;
    const int r = lane >> 2, c = lane & 3;
    #pragma unroll
    for (int x = 0; x < 2; x++) {
        #pragma unroll
        for (int jj = 0; jj < 4; jj++) {
            stage[ r    *20 + 2*c    ] = acc[x][2*jj][0];
            stage[ r    *20 + 2*c + 1] = acc[x][2*jj][1];
            stage[(r+8) *20 + 2*c    ] = acc[x][2*jj][2];
            stage[(r+8) *20 + 2*c + 1] = acc[x][2*jj][3];
            stage[ r    *20 + 8 + 2*c    ] = acc[x][2*jj+1][0];
            stage[ r    *20 + 8 + 2*c + 1] = acc[x][2*jj+1][1];
            stage[(r+8) *20 + 8 + 2*c    ] = acc[x][2*jj+1][2];
            stage[(r+8) *20 + 8 + 2*c + 1] = acc[x][2*jj+1][3];
            __syncwarp();
            #pragma unroll
            for (int e = 0; e < 8; e++) {
                int idx = e*32 + lane;
                int rr = idx >> 4, cc = idx & 15;
                int gm = bm*128 + wm*32 + x*16 + rr;
                int gn = bn*128 + wn*64 + jj*16 + cc;
                float v = stage[rr*20 + cc] + __ldg(&bias[gn]);
                if (MODE == 0) {
                    int b = gm >> 11, t = gm & 2047;
                    int part = gn >> 10, rem = gn & 1023;
                    int h = rem >> 6, d = rem & 63;
                    size_t off = (((size_t)(b*NH + h))*SEQ + t)*DK + d;
                    if (part == 0)      g_Qh[off] = __float2half_rn(v * 0.1803368801f); // 0.125*log2(e)
                    else if (part == 1) g_Kh[off] = __float2half_rn(v);
                    else                g_Vh[off] = __float2half_rn(v);
                } else {
                    Cout[(size_t)gm*DM + gn] = v;
                }
            }
            __syncwarp();
        }
    }
}

// ============================================================
// FlashAttention-2, all-fp16, 6-stage KV pipeline with ONE
// __syncthreads per 2 key-tiles. Prefetch of tiles kt+4/kt+5 is
// issued between the S-mma and softmax of the first tile of the
// pair. S = Q K^T with K B-fragments via ldmatrix.x4; softmax in
// base-2; P fp16 regs; O += P V via ldmatrix.trans.
// ============================================================
#define KV_LD 72                       // halves per K/V row
#define KVBUF (64*KV_LD)               // halves per stage
#define ASTAGES 6
#define ATTN_SMEM (2*ASTAGES*KVBUF*2)  // 6 x K + 6 x V = 110592 B

__global__ __launch_bounds__(256, 2)
void attn_kernel()
{
    extern __shared__ char smraw[];
    __half* Ksm = (__half*)smraw;                 // 6 x 64 x 72
    __half* Vsm = Ksm + ASTAGES*KVBUF;            // 6 x 64 x 72

    const int tid  = threadIdx.x;
    const int warp = tid >> 5;
    const int lane = tid & 31;
    const int r    = lane >> 2;      // 0..7
    const int c    = lane & 3;       // 0..3
    const int q0   = blockIdx.x * 128;
    const int h    = blockIdx.y;
    const int b    = blockIdx.z;
    const size_t headbase = ((size_t)(b*NH + h))*SEQ*DK;

    // ---- Q fragments (fp16, pre-scaled incl. log2e) from gmem ----
    unsigned qf[4][4];
    {
        const __half* q_r0 = g_Qh + headbase + (size_t)(q0 + warp*16 + r)*DK;
        const __half* q_r1 = q_r0 + 8*DK;
        #pragma unroll
        for (int s = 0; s < 4; s++) {
            qf[s][0] = *(const unsigned*)(q_r0 + 16*s + 2*c);
            qf[s][1] = *(const unsigned*)(q_r1 + 16*s + 2*c);
            qf[s][2] = *(const unsigned*)(q_r0 + 16*s + 2*c + 8);
            qf[s][3] = *(const unsigned*)(q_r1 + 16*s + 2*c + 8);
        }
    }

    float Oacc[8][4];
    #pragma unroll
    for (int j=0;j<8;j++)
        #pragma unroll
        for (int e=0;e<4;e++) Oacc[j][e] = 0.0f;
    float mrow[2] = {-CUDART_INF_F, -CUDART_INF_F};
    float lrow[2] = {0.0f, 0.0f};

    const uint32_t kbase0 = smem_u32(Ksm);
    const uint32_t vbase0 = smem_u32(Vsm);

    auto preload = [&](int kt) {
        const int st = kt % ASTAGES;
        const size_t kb = headbase + (size_t)kt*64*DK;
        const uint32_t kd = kbase0 + (uint32_t)(st*KVBUF*2);
        const uint32_t vd = vbase0 + (uint32_t)(st*KVBUF*2);
        #pragma unroll
        for (int it = 0; it < 2; it++) {             // K: 512 x 16B
            int idx = tid + it*256;
            int row = idx >> 3, seg = idx & 7;
            cp_async16(kd + row*KV_LD*2 + seg*16, g_Kh + kb + (size_t)row*DK + seg*8);
        }
        #pragma unroll
        for (int it = 0; it < 2; it++) {             // V: 512 x 16B
            int idx = tid + it*256;
            int row = idx >> 3, seg = idx & 7;
            cp_async16(vd + row*KV_LD*2 + seg*16, g_Vh + kb + (size_t)row*DK + seg*8);
        }
    };

    preload(0); cp_commit();
    preload(1); cp_commit();
    preload(2); cp_commit();
    preload(3); cp_commit();

    const int n_off = ((lane >> 4) << 3) + (lane & 7);   // (group>>1)*8 + row
    const int c_off = ((lane >> 3) & 1) << 3;            // (group&1)*8
    const int t  = lane >> 3;
    const int rr = lane & 7;

    // one key-tile: S-mma, (optional prefetch of kt+4/kt+5), softmax, PV
    auto do_tile = [&](int kt, bool pf) {
        const int st = kt % ASTAGES;
        const uint32_t kb32 = kbase0 + (uint32_t)(st*KVBUF*2);
        const uint32_t vb   = vbase0 + (uint32_t)(st*KVBUF*2);

        // ---- S = Q K^T ----
        float Sacc[8][4];
        #pragma unroll
        for (int j=0;j<8;j++)
            #pragma unroll
            for (int e=0;e<4;e++) Sacc[j][e] = 0.0f;
        #pragma unroll
        for (int s = 0; s < 4; s++) {
            #pragma unroll
            for (int jp = 0; jp < 4; jp++) {
                uint32_t addr = kb32 + (uint32_t)((((16*jp + n_off)*KV_LD) + 16*s + c_off)*2);
                unsigned b0,b1,b2,b3;
                ldsm_x4(b0, b1, b2, b3, addr);
                mma_f16(Sacc[2*jp  ], qf[s], b0, b1);
                mma_f16(Sacc[2*jp+1], qf[s], b2, b3);
            }
        }

        // prefetch pair kt+4, kt+5 (targets (kt-2)%6, (kt-1)%6 — last
        // read before this pair's barrier; disjoint from kt, kt+1)
        if (pf && kt + 4 < SEQ/64) {
            preload(kt+4); cp_commit();
            preload(kt+5); cp_commit();
        }

        // ---- online softmax (base-2) ----
        float mx0 = Sacc[0][0], mx1 = Sacc[0][2];
        #pragma unroll
        for (int j=0;j<8;j++) {
            mx0 = fmaxf(mx0, fmaxf(Sacc[j][0], Sacc[j][1]));
            mx1 = fmaxf(mx1, fmaxf(Sacc[j][2], Sacc[j][3]));
        }
        mx0 = fmaxf(mx0, __shfl_xor_sync(0xffffffffu, mx0, 1));
        mx0 = fmaxf(mx0, __shfl_xor_sync(0xffffffffu, mx0, 2));
        mx1 = fmaxf(mx1, __shfl_xor_sync(0xffffffffu, mx1, 1));
        mx1 = fmaxf(mx1, __shfl_xor_sync(0xffffffffu, mx1, 2));
        float mn0 = fmaxf(mrow[0], mx0), mn1 = fmaxf(mrow[1], mx1);
        float al0 = exp2f(mrow[0] - mn0), al1 = exp2f(mrow[1] - mn1);
        mrow[0] = mn0; mrow[1] = mn1;

        unsigned ph[16];
        float sum0 = 0.0f, sum1 = 0.0f;
        #pragma unroll
        for (int j = 0; j < 8; j++) {
            float p0 = exp2f(Sacc[j][0] - mn0);
            float p1 = exp2f(Sacc[j][1] - mn0);
            float p2 = exp2f(Sacc[j][2] - mn1);
            float p3 = exp2f(Sacc[j][3] - mn1);
            sum0 += p0 + p1; sum1 += p2 + p3;
            ph[2*j  ] = h2_as_u32(__floats2half2_rn(p0, p1));
            ph[2*j+1] = h2_as_u32(__floats2half2_rn(p2, p3));
        }
        sum0 += __shfl_xor_sync(0xffffffffu, sum0, 1);
        sum0 += __shfl_xor_sync(0xffffffffu, sum0, 2);
        sum1 += __shfl_xor_sync(0xffffffffu, sum1, 1);
        sum1 += __shfl_xor_sync(0xffffffffu, sum1, 2);
        lrow[0] = lrow[0]*al0 + sum0;
        lrow[1] = lrow[1]*al1 + sum1;
        #pragma unroll
        for (int j=0;j<8;j++) {
            Oacc[j][0] *= al0; Oacc[j][1] *= al0;
            Oacc[j][2] *= al1; Oacc[j][3] *= al1;
        }

        // ---- O += P V ----
        #pragma unroll
        for (int s = 0; s < 4; s++) {
            const unsigned* af = &ph[4*s];
            #pragma unroll
            for (int g = 0; g < 4; g++) {
                uint32_t addr = vb + (uint32_t)(((16*s + (t&1)*8 + rr)*KV_LD + (t>>1)*8 + g*16)*2);
                unsigned r0,r1,r2,r3;
                asm volatile(
                    "ldmatrix.sync.aligned.m8n8.x4.trans.shared.b16 {%0,%1,%2,%3}, [%4];\n"
                    : "=r"(r0),"=r"(r1),"=r"(r2),"=r"(r3) : "r"(addr));
                mma_f16(Oacc[2*g  ], af, r0, r1);
                mma_f16(Oacc[2*g+1], af, r2, r3);
            }
        }
    };

    #pragma unroll 1
    for (int kt = 0; kt < SEQ/64; kt += 2) {
        if (kt < SEQ/64 - 2) cp_wait<2>(); else cp_wait<0>();
        __syncthreads();
        do_tile(kt,     true);
        do_tile(kt + 1, false);
    }

    // ---- normalize + write ctx fp16 [B,T,DM] ----
    {
        float inv0 = 1.0f / lrow[0];
        float inv1 = 1.0f / lrow[1];
        __half* row0 = g_ctxh + ((size_t)(b*SEQ + q0 + warp*16 + r    ))*DM + h*DK;
        __half* row1 = g_ctxh + ((size_t)(b*SEQ + q0 + warp*16 + r + 8))*DM + h*DK;
        #pragma unroll
        for (int j = 0; j < 8; j++) {
            *(__half2*)(row0 + 8*j + 2*c) = __floats2half2_rn(Oacc[j][0]*inv0, Oacc[j][1]*inv0);
            *(__half2*)(row1 + 8*j + 2*c) = __floats2half2_rn(Oacc[j][2]*inv1, Oacc[j][3]*inv1);
        }
    }
}

// ============================================================
extern "C" void kernel_launch(void* const* d_in, const int* in_sizes, int n_in,
                              void* d_out, int out_size)
{
    (void)in_sizes; (void)n_in; (void)out_size;
    const float* x     = (const float*)d_in[0];
    const float* w_qkv = (const float*)d_in[1];
    const float* b_qkv = (const float*)d_in[2];
    const float* w_out = (const float*)d_in[3];
    const float* b_out = (const float*)d_in[4];
    float* out = (float*)d_out;

    cudaFuncSetAttribute(gemm_f16_kernel<0>, cudaFuncAttributeMaxDynamicSharedMemorySize, GEMM_SMEM);
    cudaFuncSetAttribute(gemm_f16_kernel<1>, cudaFuncAttributeMaxDynamicSharedMemorySize, GEMM_SMEM);
    cudaFuncSetAttribute(attn_kernel, cudaFuncAttributeMaxDynamicSharedMemorySize, ATTN_SMEM);

    void *xh, *wqkvh, *wouth;
    cudaGetSymbolAddress(&xh,    g_xh);
    cudaGetSymbolAddress(&wqkvh, g_wqkvh);
    cudaGetSymbolAddress(&wouth, g_wouth);

    // 0) fused fp32 -> fp16 prepass (one launch)
    prep_kernel<<<1024, 256>>>((const float4*)x, (const float4*)w_qkv, (const float4*)w_out,
                               (uint2*)xh, (uint2*)wqkvh, (uint2*)wouth);

    // 1) QKV projection -> Q/K/V fp16 scratch
    gemm_f16_kernel<0><<<dim3(3*DM/128, M_TOT/128), 256, GEMM_SMEM>>>(b_qkv, nullptr);
    // 2) attention -> ctx fp16 scratch
    attn_kernel<<<dim3(SEQ/128, NH, BATCH), 256, ATTN_SMEM>>>();
    // 3) output projection -> d_out fp32
    gemm_f16_kernel<1><<<dim3(DM/128, M_TOT/128), 256, GEMM_SMEM>>>(b_out, out);
}